// round 14
// baseline (speedup 1.0000x reference)
#include <cuda_runtime.h>
#include <cstdint>

#define Bn   64
#define Sn   1024
#define Dn   1024
#define NT   34      // tags incl BOS
#define NA   33      // active states (BOS column dead)
#define BOSI 33

// -------- scratch (static device allocations) --------
__device__ float  g_pm[Bn][NA];                      // forward p at mid
__device__ float  g_vm[Bn][NA];                      // backward v at mid
__device__ int    g_cntf[Bn], g_cntb[Bn];
__device__ float  g_score[Bn];

// ============================ GEMM: scalar FFMA, 2 rows/thread, staged A ============================
// 512 CTAs x 64 threads, 2 rows/thread (stride 64), KT=32.
// A tile [128][32] staged coalesced through smem (nL=4 per warp LDG instead of 32).
// W tile [32][36] broadcast from smem. Register double-buffer for both (2 BAR/tile).
#define KTG 32

#define GU2(A0, A1, KK) do{                                                  \
    const float4* wr_ = (const float4*)(&Wt[KK][0]);                         \
    _Pragma("unroll")                                                        \
    for (int q = 0; q < 8; q++){                                             \
        float4 w_ = wr_[q];                                                  \
        acc0[4*q+0] += (A0)*w_.x; acc0[4*q+1] += (A0)*w_.y;                  \
        acc0[4*q+2] += (A0)*w_.z; acc0[4*q+3] += (A0)*w_.w;                  \
        acc1[4*q+0] += (A1)*w_.x; acc1[4*q+1] += (A1)*w_.y;                  \
        acc1[4*q+2] += (A1)*w_.z; acc1[4*q+3] += (A1)*w_.w;                  \
    }                                                                        \
    float wl_ = Wt[KK][32];                                                  \
    acc0[32] += (A0)*wl_; acc1[32] += (A1)*wl_;                              \
} while(0)

__global__ __launch_bounds__(64, 5)
void gemm_kernel(const float* __restrict__ em, const float* __restrict__ W,
                 const float* __restrict__ bias, float* __restrict__ out)
{
    __shared__ __align__(16) float Asf[128 * 36];   // stride 36: LDS.128 conflict-free
    __shared__ __align__(16) float Wt[KTG][36];
    __shared__ float s_bias[NA];
    __shared__ float s_out[64 * NA];

    const int tid = threadIdx.x;
    const int row_base = blockIdx.x * 128;

    if (tid < NA) s_bias[tid] = bias[tid];

    float acc0[NA], acc1[NA];
    #pragma unroll
    for (int j = 0; j < NA; j++){ acc0[j] = 0.f; acc1[j] = 0.f; }

    const float4* ap = (const float4*)em;           // global, float4 units (row stride 256)

    float4 areg[16];
    float  wreg[18];

    // ---- prologue: tile 0 -> regs -> smem ----
    #pragma unroll
    for (int q = 0; q < 16; q++){
        int f = q*64 + tid, r = f >> 3, c = f & 7;
        areg[q] = ap[(size_t)(row_base + r) * 256 + c];
    }
    #pragma unroll
    for (int q = 0; q < 18; q++){
        int i = q*64 + tid, kk = i / 36, j = i - kk*36;
        wreg[q] = (j < NA) ? W[(size_t)kk * NT + j] : 0.f;
    }
    #pragma unroll
    for (int q = 0; q < 16; q++){
        int f = q*64 + tid, r = f >> 3, c = f & 7;
        *(float4*)&Asf[r*36 + c*4] = areg[q];
    }
    #pragma unroll
    for (int q = 0; q < 18; q++){
        int i = q*64 + tid, kk = i / 36, j = i - kk*36;
        Wt[kk][j] = wreg[q];
    }
    __syncthreads();

    #pragma unroll 1
    for (int kt = 0; kt < Dn/KTG; kt++){
        const bool more = (kt < Dn/KTG - 1);
        if (more){
            // prefetch next tile into regs (hidden behind compute)
            #pragma unroll
            for (int q = 0; q < 16; q++){
                int f = q*64 + tid, r = f >> 3, c = f & 7;
                areg[q] = ap[(size_t)(row_base + r) * 256 + (kt+1)*8 + c];
            }
            const float* wsrc = W + (size_t)(kt+1) * KTG * NT;
            #pragma unroll
            for (int q = 0; q < 18; q++){
                int i = q*64 + tid, kk = i / 36, j = i - kk*36;
                wreg[q] = (j < NA) ? wsrc[(size_t)kk * NT + j] : 0.f;
            }
        }

        // ---- compute tile kt from smem ----
        #pragma unroll
        for (int k4 = 0; k4 < 8; k4++){
            float4 a0 = *(const float4*)&Asf[tid*36 + k4*4];
            float4 a1 = *(const float4*)&Asf[(tid + 64)*36 + k4*4];
            GU2(a0.x, a1.x, k4*4+0);
            GU2(a0.y, a1.y, k4*4+1);
            GU2(a0.z, a1.z, k4*4+2);
            GU2(a0.w, a1.w, k4*4+3);
        }

        if (more){
            __syncthreads();
            #pragma unroll
            for (int q = 0; q < 16; q++){
                int f = q*64 + tid, r = f >> 3, c = f & 7;
                *(float4*)&Asf[r*36 + c*4] = areg[q];
            }
            #pragma unroll
            for (int q = 0; q < 18; q++){
                int i = q*64 + tid, kk = i / 36, j = i - kk*36;
                Wt[kk][j] = wreg[q];
            }
            __syncthreads();
        }
    }

    // ---- epilogue: 2 chunks of 64 rows, staged through smem for coalesced stores ----
    #pragma unroll
    for (int r = 0; r < 2; r++){
        const float* acc = (r == 0) ? acc0 : acc1;
        #pragma unroll
        for (int j = 0; j < NA; j++)
            s_out[tid * NA + j] = acc[j] + s_bias[j];
        __syncthreads();
        float* obase = out + 1 + ((size_t)blockIdx.x * 128 + 64*r) * NA;
        #pragma unroll
        for (int q = 0; q < NA; q++)
            obase[tid + 64*q] = s_out[tid + 64*q];
        __syncthreads();
    }
}

// ============================ CRF scan (fwd/bwd) + gold score ============================
// Reads logits from out[b][t][j] (coalesced across lanes), exp applied inline.
#define SCAN_BODY(PL, PH, EMJ, EM32, MK, DOT_W)                                \
{                                                                              \
    float p0v = __shfl_sync(0xffffffffu, PL, 0);                               \
    unsigned eb = __float_as_uint(p0v) >> 23;                                  \
    cnt += (int)eb - 127;                                                      \
    float scl = __uint_as_float((254u - eb) << 23);                            \
    float al0=0.f, al1=0.f, al2=0.f, al3=0.f;                                  \
    float ahh0=0.f, ahh1=0.f, ahh2=0.f, ahh3=0.f;                              \
    float wl = (DOT_W) ? (PL) * (EMJ)  : (PL);                                 \
    float wh = (DOT_W) ? (PH) * (EM32) : (PH);                                 \
    _Pragma("unroll")                                                          \
    for (int i = 0; i < 32; i += 4){                                           \
        float v0 = __shfl_sync(0xffffffffu, wl, i);                            \
        float v1 = __shfl_sync(0xffffffffu, wl, i+1);                          \
        float v2 = __shfl_sync(0xffffffffu, wl, i+2);                          \
        float v3 = __shfl_sync(0xffffffffu, wl, i+3);                          \
        al0 += v0*E_l[i];   ahh0 += v0*E_h[i];                                 \
        al1 += v1*E_l[i+1]; ahh1 += v1*E_h[i+1];                               \
        al2 += v2*E_l[i+2]; ahh2 += v2*E_h[i+2];                               \
        al3 += v3*E_l[i+3]; ahh3 += v3*E_h[i+3];                               \
    }                                                                          \
    al0 += wh*E_l[32]; ahh0 += wh*E_h[32];                                     \
    float sl = (al0+al1)+(al2+al3);                                            \
    float sh = (ahh0+ahh1)+(ahh2+ahh3);                                        \
    float nl, nh;                                                              \
    if (DOT_W){ nl = sl*scl; nh = sh*scl; }                                    \
    else      { nl = sl*((EMJ)*scl); nh = sh*((EM32)*scl); }                   \
    if ((MK) == 0.f){ nl = (PL)*scl; nh = (PH)*scl; }                          \
    PL = nl; PH = nh;                                                          \
}

__global__ __launch_bounds__(32)
void scan_kernel(const float* __restrict__ T, const float* __restrict__ mask,
                 const int* __restrict__ tags, const float* __restrict__ outp)
{
    const int blk = blockIdx.x;
    const int j   = threadIdx.x;

    if (blk >= 2 * Bn){
        // ---- gold-path score for batch (blk - 2*Bn) ----
        int b = blk - 2 * Bn, lane = j;
        float partial = 0.f;
        for (int t = lane; t < Sn; t += 32){
            int   tg = tags[b*Sn + t];
            float e  = outp[1 + ((size_t)b*Sn + t)*NA + tg];
            if (t == 0){
                partial += T[BOSI*NT + tg] + e;
            } else {
                int tgp = tags[b*Sn + t - 1];
                partial += (e + T[tgp*NT + tg]) * mask[b*Sn + t];
            }
        }
        #pragma unroll
        for (int o = 16; o; o >>= 1) partial += __shfl_xor_sync(0xffffffffu, partial, o);
        if (lane == 0) g_score[b] = partial;
        return;
    }

    const int b   = blk >> 1;
    const int dir = blk & 1;

    float E_l[NA], E_h[NA];
    if (dir == 0){
        #pragma unroll
        for (int i = 0; i < NA; i++){
            E_l[i] = __expf(T[i*NT + j]);
            E_h[i] = __expf(T[i*NT + 32]);
        }
    } else {
        #pragma unroll
        for (int s = 0; s < NA; s++){
            E_l[s] = __expf(T[j*NT + s]);
            E_h[s] = __expf(T[32*NT + s]);
        }
    }

    const float* eb_base = outp + 1 + (size_t)b * Sn * NA;   // [t][j], lane-coalesced
    const float4* mp4 = (const float4*)(mask + (size_t)b * Sn);

    int cnt = 0;

    if (dir == 0){
        float emc[4], e3c[4];
        #pragma unroll
        for (int d = 0; d < 4; d++){
            emc[d] = eb_base[d*NA + j];
            e3c[d] = eb_base[d*NA + 32];
        }
        float4 mkc = mp4[0];

        float pl = __expf(T[BOSI*NT + j])  * __expf(emc[0]);
        float ph = __expf(T[BOSI*NT + 32]) * __expf(e3c[0]);

        float emn[4], e3n[4]; float4 mkn;
        #pragma unroll
        for (int d = 0; d < 4; d++){
            emn[d] = eb_base[(4 + d)*NA + j];
            e3n[d] = eb_base[(4 + d)*NA + 32];
        }
        mkn = mp4[1];

        SCAN_BODY(pl, ph, __expf(emc[1]), __expf(e3c[1]), mkc.y, 0);
        SCAN_BODY(pl, ph, __expf(emc[2]), __expf(e3c[2]), mkc.z, 0);
        SCAN_BODY(pl, ph, __expf(emc[3]), __expf(e3c[3]), mkc.w, 0);

        for (int g = 1; g < 128; g++){
            #pragma unroll
            for (int d = 0; d < 4; d++){ emc[d] = emn[d]; e3c[d] = e3n[d]; }
            mkc = mkn;
            if (g + 1 < 128){
                #pragma unroll
                for (int d = 0; d < 4; d++){
                    emn[d] = eb_base[((g+1)*4 + d)*NA + j];
                    e3n[d] = eb_base[((g+1)*4 + d)*NA + 32];
                }
                mkn = mp4[g+1];
            }
            SCAN_BODY(pl, ph, __expf(emc[0]), __expf(e3c[0]), mkc.x, 0);
            SCAN_BODY(pl, ph, __expf(emc[1]), __expf(e3c[1]), mkc.y, 0);
            SCAN_BODY(pl, ph, __expf(emc[2]), __expf(e3c[2]), mkc.z, 0);
            SCAN_BODY(pl, ph, __expf(emc[3]), __expf(e3c[3]), mkc.w, 0);
        }
        g_pm[b][j] = pl;
        if (j == 0){ g_pm[b][32] = ph; g_cntf[b] = cnt; }
    } else {
        float vl = 1.f, vh = 1.f;

        float emc[4], e3c[4];
        #pragma unroll
        for (int d = 0; d < 4; d++){
            emc[d] = eb_base[(255*4 + d)*NA + j];
            e3c[d] = eb_base[(255*4 + d)*NA + 32];
        }
        float4 mkc = mp4[255];

        float emn[4], e3n[4]; float4 mkn;

        for (int g = 255; g >= 128; g--){
            if (g > 128){
                #pragma unroll
                for (int d = 0; d < 4; d++){
                    emn[d] = eb_base[((g-1)*4 + d)*NA + j];
                    e3n[d] = eb_base[((g-1)*4 + d)*NA + 32];
                }
                mkn = mp4[g-1];
            }
            SCAN_BODY(vl, vh, __expf(emc[3]), __expf(e3c[3]), mkc.w, 1);
            SCAN_BODY(vl, vh, __expf(emc[2]), __expf(e3c[2]), mkc.z, 1);
            SCAN_BODY(vl, vh, __expf(emc[1]), __expf(e3c[1]), mkc.y, 1);
            SCAN_BODY(vl, vh, __expf(emc[0]), __expf(e3c[0]), mkc.x, 1);
            #pragma unroll
            for (int d = 0; d < 4; d++){ emc[d] = emn[d]; e3c[d] = e3n[d]; }
            mkc = mkn;
        }
        g_vm[b][j] = vl;
        if (j == 0){ g_vm[b][32] = vh; g_cntb[b] = cnt; }
    }
}

// ============================ combine + loss ============================
__global__ __launch_bounds__(32)
void loss_kernel(float* __restrict__ out)
{
    int lane = threadIdx.x;
    double v = 0.0;
    #pragma unroll
    for (int h = 0; h < 2; h++){
        int b = lane + 32*h;
        double dot = 0.0;
        #pragma unroll
        for (int i = 0; i < NA; i++) dot += (double)g_pm[b][i] * (double)g_vm[b][i];
        double part = (double)(g_cntf[b] + g_cntb[b]) * 0.6931471805599453 + log(dot);
        v += part - (double)g_score[b];
    }
    #pragma unroll
    for (int o = 16; o; o >>= 1) v += __shfl_xor_sync(0xffffffffu, v, o);
    if (lane == 0) out[0] = (float)v;
}

// ============================ launch ============================
extern "C" void kernel_launch(void* const* d_in, const int* in_sizes, int n_in,
                              void* d_out, int out_size)
{
    const float* em   = (const float*)d_in[0];   // (B,S,D)
    const int*   tags = (const int*)  d_in[1];   // (B,S)
    const float* mask = (const float*)d_in[2];   // (B,S)
    const float* W    = (const float*)d_in[3];   // (D,N)
    const float* bias = (const float*)d_in[4];   // (N,)
    const float* T    = (const float*)d_in[5];   // (N,N)
    float* out = (float*)d_out;                  // [loss, logits(B,S,33)]

    gemm_kernel <<<(Bn*Sn)/128, 64>>>(em, W, bias, out);
    scan_kernel <<<3*Bn, 32>>>(T, mask, tags, out);
    loss_kernel <<<1, 32>>>(out);
}

// round 15
// speedup vs baseline: 1.3344x; 1.3344x over previous
#include <cuda_runtime.h>
#include <cstdint>

#define Bn   64
#define Sn   1024
#define Dn   1024
#define NT   34      // tags incl BOS
#define NA   33      // active states (BOS column dead)
#define BOSI 33

typedef unsigned long long u64;

// -------- scratch (static device allocations) --------
__device__ float  g_pm[Bn][NA];                      // forward p at mid
__device__ float  g_vm[Bn][NA];                      // backward v at mid
__device__ int    g_cntf[Bn], g_cntb[Bn];
__device__ float  g_score[Bn];

// ============================ f32x2 helpers ============================
__device__ __forceinline__ void ffma2(u64& d, u64 a, u64 b){
    asm("fma.rn.f32x2 %0, %1, %2, %0;" : "+l"(d) : "l"(a), "l"(b));
}
__device__ __forceinline__ u64 pack2(float x){           // {x, x}
    u64 r; asm("mov.b64 %0, {%1, %1};" : "=l"(r) : "f"(x)); return r;
}
__device__ __forceinline__ void unpack2(u64 v, float& lo, float& hi){
    asm("mov.b64 {%0, %1}, %2;" : "=f"(lo), "=f"(hi) : "l"(v));
}

// ============================ GEMM: f32x2 FMA, 2 rows/thread ============================
// 512 CTAs x 64 threads, 2 rows/thread (stride 64), KT=16. R13 structure:
// W double-buffered in smem (reg-staged, 1 sync/tile); A prefetched in regs.
// Inner product on packed column-pairs: 34 FFMA2 + 5 LDS per k-step (vs 66+9).
#define KTG 16

#define GU2P(A0, A1, KK) do{                                                 \
    u64 pa0 = pack2(A0), pa1 = pack2(A1);                                    \
    const ulonglong2* wr_ = (const ulonglong2*)(&Wt[KK][0]);                 \
    _Pragma("unroll")                                                        \
    for (int q = 0; q < 8; q++){                                             \
        ulonglong2 w_ = wr_[q];                                              \
        ffma2(acc0[2*q],   pa0, w_.x); ffma2(acc0[2*q+1], pa0, w_.y);        \
        ffma2(acc1[2*q],   pa1, w_.x); ffma2(acc1[2*q+1], pa1, w_.y);        \
    }                                                                        \
    u64 wl_ = ((const u64*)&Wt[KK][0])[16];                                  \
    ffma2(acc0[16], pa0, wl_); ffma2(acc1[16], pa1, wl_);                    \
} while(0)

__global__ __launch_bounds__(64, 4)
void gemm_kernel(const float* __restrict__ em, const float* __restrict__ W,
                 const float* __restrict__ bias, float* __restrict__ out)
{
    __shared__ __align__(16) u64 Wt[KTG][18];    // 17 pairs used (cols 0..33), stride 18
    __shared__ float s_bias[NA];
    __shared__ float s_out[64 * NA];

    const int tid = threadIdx.x;
    const int row0 = blockIdx.x * 128 + tid;      // rows: row0, row0+64

    if (tid < NA) s_bias[tid] = bias[tid];

    u64 acc0[17], acc1[17];
    #pragma unroll
    for (int j = 0; j < 17; j++){ acc0[j] = 0ull; acc1[j] = 0ull; }

    const float4* ar0 = (const float4*)(em + (size_t)(row0)      * Dn);
    const float4* ar1 = (const float4*)(em + (size_t)(row0 + 64) * Dn);

    float* Wf = (float*)&Wt[0][0];                // float view: row kk at kk*36

    // prologue: W tile 0 (576 floats, 9/thread); A tile 0 -> regs
    #pragma unroll
    for (int q = 0; q < 9; q++){
        int i = tid + 64*q;
        int kk = i / 36, j = i - kk*36;
        Wf[kk*36 + j] = (j < NT) ? W[(size_t)kk * NT + j] : 0.f;
    }
    float4 ab0[4], ab1[4], an0[4], an1[4];
    #pragma unroll
    for (int q = 0; q < 4; q++){ ab0[q] = ar0[q]; ab1[q] = ar1[q]; }
    __syncthreads();

    #pragma unroll 1
    for (int kt = 0; kt < Dn/KTG; kt++){
        const bool more = (kt < Dn/KTG - 1);

        float wreg[9];
        if (more){
            const float* wsrc = W + (size_t)(kt+1) * KTG * NT;
            #pragma unroll
            for (int q = 0; q < 9; q++){
                int i = tid + 64*q;
                int kk = i / 36, j = i - kk*36;
                wreg[q] = (j < NT) ? wsrc[(size_t)kk * NT + j] : 0.f;
            }
            #pragma unroll
            for (int q = 0; q < 4; q++){
                an0[q] = ar0[(kt+1)*4 + q];
                an1[q] = ar1[(kt+1)*4 + q];
            }
        }

        #pragma unroll
        for (int kk4 = 0; kk4 < 4; kk4++){
            float4 a0 = ab0[kk4], a1 = ab1[kk4];
            GU2P(a0.x, a1.x, kk4*4+0);
            GU2P(a0.y, a1.y, kk4*4+1);
            GU2P(a0.z, a1.z, kk4*4+2);
            GU2P(a0.w, a1.w, kk4*4+3);
        }

        if (more){
            __syncthreads();
            #pragma unroll
            for (int q = 0; q < 9; q++){
                int i = tid + 64*q;
                int kk = i / 36, j = i - kk*36;
                Wf[kk*36 + j] = wreg[q];
            }
            __syncthreads();
            #pragma unroll
            for (int q = 0; q < 4; q++){ ab0[q] = an0[q]; ab1[q] = an1[q]; }
        }
    }

    // epilogue: 2 chunks of 64 rows, staged through smem for coalesced stores
    #pragma unroll
    for (int r = 0; r < 2; r++){
        const u64* acc = (r == 0) ? acc0 : acc1;
        #pragma unroll
        for (int j2 = 0; j2 < 17; j2++){
            float lo, hi;
            unpack2(acc[j2], lo, hi);
            int jl = 2*j2, jh = 2*j2 + 1;
            s_out[tid * NA + jl] = lo + s_bias[jl];
            if (jh < NA) s_out[tid * NA + jh] = hi + s_bias[jh];
        }
        __syncthreads();
        float* obase = out + 1 + ((size_t)blockIdx.x * 128 + 64*r) * NA;
        #pragma unroll
        for (int q = 0; q < NA; q++)
            obase[tid + 64*q] = s_out[tid + 64*q];
        __syncthreads();
    }
}

// ============================ CRF scan (fwd/bwd) + gold score ============================
// Reads logits from out[b][t][j] (coalesced across lanes), exp applied inline.
#define SCAN_BODY(PL, PH, EMJ, EM32, MK, DOT_W)                                \
{                                                                              \
    float p0v = __shfl_sync(0xffffffffu, PL, 0);                               \
    unsigned eb = __float_as_uint(p0v) >> 23;                                  \
    cnt += (int)eb - 127;                                                      \
    float scl = __uint_as_float((254u - eb) << 23);                            \
    float al0=0.f, al1=0.f, al2=0.f, al3=0.f;                                  \
    float ahh0=0.f, ahh1=0.f, ahh2=0.f, ahh3=0.f;                              \
    float wl = (DOT_W) ? (PL) * (EMJ)  : (PL);                                 \
    float wh = (DOT_W) ? (PH) * (EM32) : (PH);                                 \
    _Pragma("unroll")                                                          \
    for (int i = 0; i < 32; i += 4){                                           \
        float v0 = __shfl_sync(0xffffffffu, wl, i);                            \
        float v1 = __shfl_sync(0xffffffffu, wl, i+1);                          \
        float v2 = __shfl_sync(0xffffffffu, wl, i+2);                          \
        float v3 = __shfl_sync(0xffffffffu, wl, i+3);                          \
        al0 += v0*E_l[i];   ahh0 += v0*E_h[i];                                 \
        al1 += v1*E_l[i+1]; ahh1 += v1*E_h[i+1];                               \
        al2 += v2*E_l[i+2]; ahh2 += v2*E_h[i+2];                               \
        al3 += v3*E_l[i+3]; ahh3 += v3*E_h[i+3];                               \
    }                                                                          \
    al0 += wh*E_l[32]; ahh0 += wh*E_h[32];                                     \
    float sl = (al0+al1)+(al2+al3);                                            \
    float sh = (ahh0+ahh1)+(ahh2+ahh3);                                        \
    float nl, nh;                                                              \
    if (DOT_W){ nl = sl*scl; nh = sh*scl; }                                    \
    else      { nl = sl*((EMJ)*scl); nh = sh*((EM32)*scl); }                   \
    if ((MK) == 0.f){ nl = (PL)*scl; nh = (PH)*scl; }                          \
    PL = nl; PH = nh;                                                          \
}

__global__ __launch_bounds__(32)
void scan_kernel(const float* __restrict__ T, const float* __restrict__ mask,
                 const int* __restrict__ tags, const float* __restrict__ outp)
{
    const int blk = blockIdx.x;
    const int j   = threadIdx.x;

    if (blk >= 2 * Bn){
        // ---- gold-path score for batch (blk - 2*Bn) ----
        int b = blk - 2 * Bn, lane = j;
        float partial = 0.f;
        for (int t = lane; t < Sn; t += 32){
            int   tg = tags[b*Sn + t];
            float e  = outp[1 + ((size_t)b*Sn + t)*NA + tg];
            if (t == 0){
                partial += T[BOSI*NT + tg] + e;
            } else {
                int tgp = tags[b*Sn + t - 1];
                partial += (e + T[tgp*NT + tg]) * mask[b*Sn + t];
            }
        }
        #pragma unroll
        for (int o = 16; o; o >>= 1) partial += __shfl_xor_sync(0xffffffffu, partial, o);
        if (lane == 0) g_score[b] = partial;
        return;
    }

    const int b   = blk >> 1;
    const int dir = blk & 1;

    float E_l[NA], E_h[NA];
    if (dir == 0){
        #pragma unroll
        for (int i = 0; i < NA; i++){
            E_l[i] = __expf(T[i*NT + j]);
            E_h[i] = __expf(T[i*NT + 32]);
        }
    } else {
        #pragma unroll
        for (int s = 0; s < NA; s++){
            E_l[s] = __expf(T[j*NT + s]);
            E_h[s] = __expf(T[32*NT + s]);
        }
    }

    const float* eb_base = outp + 1 + (size_t)b * Sn * NA;   // [t][j], lane-coalesced
    const float4* mp4 = (const float4*)(mask + (size_t)b * Sn);

    int cnt = 0;

    if (dir == 0){
        float emc[4], e3c[4];
        #pragma unroll
        for (int d = 0; d < 4; d++){
            emc[d] = eb_base[d*NA + j];
            e3c[d] = eb_base[d*NA + 32];
        }
        float4 mkc = mp4[0];

        float pl = __expf(T[BOSI*NT + j])  * __expf(emc[0]);
        float ph = __expf(T[BOSI*NT + 32]) * __expf(e3c[0]);

        float emn[4], e3n[4]; float4 mkn;
        #pragma unroll
        for (int d = 0; d < 4; d++){
            emn[d] = eb_base[(4 + d)*NA + j];
            e3n[d] = eb_base[(4 + d)*NA + 32];
        }
        mkn = mp4[1];

        SCAN_BODY(pl, ph, __expf(emc[1]), __expf(e3c[1]), mkc.y, 0);
        SCAN_BODY(pl, ph, __expf(emc[2]), __expf(e3c[2]), mkc.z, 0);
        SCAN_BODY(pl, ph, __expf(emc[3]), __expf(e3c[3]), mkc.w, 0);

        for (int g = 1; g < 128; g++){
            #pragma unroll
            for (int d = 0; d < 4; d++){ emc[d] = emn[d]; e3c[d] = e3n[d]; }
            mkc = mkn;
            if (g + 1 < 128){
                #pragma unroll
                for (int d = 0; d < 4; d++){
                    emn[d] = eb_base[((g+1)*4 + d)*NA + j];
                    e3n[d] = eb_base[((g+1)*4 + d)*NA + 32];
                }
                mkn = mp4[g+1];
            }
            SCAN_BODY(pl, ph, __expf(emc[0]), __expf(e3c[0]), mkc.x, 0);
            SCAN_BODY(pl, ph, __expf(emc[1]), __expf(e3c[1]), mkc.y, 0);
            SCAN_BODY(pl, ph, __expf(emc[2]), __expf(e3c[2]), mkc.z, 0);
            SCAN_BODY(pl, ph, __expf(emc[3]), __expf(e3c[3]), mkc.w, 0);
        }
        g_pm[b][j] = pl;
        if (j == 0){ g_pm[b][32] = ph; g_cntf[b] = cnt; }
    } else {
        float vl = 1.f, vh = 1.f;

        float emc[4], e3c[4];
        #pragma unroll
        for (int d = 0; d < 4; d++){
            emc[d] = eb_base[(255*4 + d)*NA + j];
            e3c[d] = eb_base[(255*4 + d)*NA + 32];
        }
        float4 mkc = mp4[255];

        float emn[4], e3n[4]; float4 mkn;

        for (int g = 255; g >= 128; g--){
            if (g > 128){
                #pragma unroll
                for (int d = 0; d < 4; d++){
                    emn[d] = eb_base[((g-1)*4 + d)*NA + j];
                    e3n[d] = eb_base[((g-1)*4 + d)*NA + 32];
                }
                mkn = mp4[g-1];
            }
            SCAN_BODY(vl, vh, __expf(emc[3]), __expf(e3c[3]), mkc.w, 1);
            SCAN_BODY(vl, vh, __expf(emc[2]), __expf(e3c[2]), mkc.z, 1);
            SCAN_BODY(vl, vh, __expf(emc[1]), __expf(e3c[1]), mkc.y, 1);
            SCAN_BODY(vl, vh, __expf(emc[0]), __expf(e3c[0]), mkc.x, 1);
            #pragma unroll
            for (int d = 0; d < 4; d++){ emc[d] = emn[d]; e3c[d] = e3n[d]; }
            mkc = mkn;
        }
        g_vm[b][j] = vl;
        if (j == 0){ g_vm[b][32] = vh; g_cntb[b] = cnt; }
    }
}

// ============================ combine + loss ============================
__global__ __launch_bounds__(32)
void loss_kernel(float* __restrict__ out)
{
    int lane = threadIdx.x;
    double v = 0.0;
    #pragma unroll
    for (int h = 0; h < 2; h++){
        int b = lane + 32*h;
        double dot = 0.0;
        #pragma unroll
        for (int i = 0; i < NA; i++) dot += (double)g_pm[b][i] * (double)g_vm[b][i];
        double part = (double)(g_cntf[b] + g_cntb[b]) * 0.6931471805599453 + log(dot);
        v += part - (double)g_score[b];
    }
    #pragma unroll
    for (int o = 16; o; o >>= 1) v += __shfl_xor_sync(0xffffffffu, v, o);
    if (lane == 0) out[0] = (float)v;
}

// ============================ launch ============================
extern "C" void kernel_launch(void* const* d_in, const int* in_sizes, int n_in,
                              void* d_out, int out_size)
{
    const float* em   = (const float*)d_in[0];   // (B,S,D)
    const int*   tags = (const int*)  d_in[1];   // (B,S)
    const float* mask = (const float*)d_in[2];   // (B,S)
    const float* W    = (const float*)d_in[3];   // (D,N)
    const float* bias = (const float*)d_in[4];   // (N,)
    const float* T    = (const float*)d_in[5];   // (N,N)
    float* out = (float*)d_out;                  // [loss, logits(B,S,33)]

    gemm_kernel <<<(Bn*Sn)/128, 64>>>(em, W, bias, out);
    scan_kernel <<<3*Bn, 32>>>(T, mask, tags, out);
    loss_kernel <<<1, 32>>>(out);
}

// round 17
// speedup vs baseline: 1.4643x; 1.0974x over previous
#include <cuda_runtime.h>
#include <cstdint>

#define Bn   64
#define Sn   1024
#define Dn   1024
#define NT   34      // tags incl BOS
#define NA   33      // active states (BOS column dead)
#define BOSI 33

typedef unsigned long long u64;

// -------- scratch (static device allocations) --------
__device__ float  g_pm[Bn][NA];                      // forward p at mid
__device__ float  g_vm[Bn][NA];                      // backward v at mid
__device__ int    g_cntf[Bn], g_cntb[Bn];
__device__ float  g_score[Bn];

// ============================ f32x2 helpers ============================
__device__ __forceinline__ void ffma2(u64& d, u64 a, u64 b){
    asm("fma.rn.f32x2 %0, %1, %2, %0;" : "+l"(d) : "l"(a), "l"(b));
}
__device__ __forceinline__ u64 pack2(float x){           // {x, x}
    u64 r; asm("mov.b64 %0, {%1, %1};" : "=l"(r) : "f"(x)); return r;
}
__device__ __forceinline__ void unpack2(u64 v, float& lo, float& hi){
    asm("mov.b64 {%0, %1}, %2;" : "=f"(lo), "=f"(hi) : "l"(v));
}

// ============================ GEMM: f32x2 FMA, 2 rows/thread, dbl-buffered A+W ============================
// 512 CTAs x 64 threads, 2 rows/thread (stride 64), KT=16.
// A tile [128][16] staged COALESCED through smem (4 wavefronts/warp-LDG vs 32);
// both A and W double-buffered -> single barrier per tile.
#define KTG 16
#define AST 20    // A row stride in floats (16B-aligned, conflict-free LDS/STS)

#define GU2P(A0, A1, KK) do{                                                 \
    u64 pa0 = pack2(A0), pa1 = pack2(A1);                                    \
    const ulonglong2* wr_ = (const ulonglong2*)(&Wt[cur][KK][0]);            \
    _Pragma("unroll")                                                        \
    for (int q = 0; q < 8; q++){                                             \
        ulonglong2 w_ = wr_[q];                                              \
        ffma2(acc0[2*q],   pa0, w_.x); ffma2(acc0[2*q+1], pa0, w_.y);        \
        ffma2(acc1[2*q],   pa1, w_.x); ffma2(acc1[2*q+1], pa1, w_.y);        \
    }                                                                        \
    u64 wl_ = ((const u64*)&Wt[cur][KK][0])[16];                             \
    ffma2(acc0[16], pa0, wl_); ffma2(acc1[16], pa1, wl_);                    \
} while(0)

__global__ __launch_bounds__(64, 4)
void gemm_kernel(const float* __restrict__ em, const float* __restrict__ W,
                 const float* __restrict__ bias, float* __restrict__ out)
{
    __shared__ __align__(16) float Ast[2][128 * AST];
    __shared__ __align__(16) u64   Wt[2][KTG][18];   // float view: row kk at kk*36
    __shared__ float s_bias[NA];
    __shared__ float s_out[64 * NA];

    const int tid = threadIdx.x;
    const int row_base = blockIdx.x * 128;

    if (tid < NA) s_bias[tid] = bias[tid];

    u64 acc0[17], acc1[17];
    #pragma unroll
    for (int j = 0; j < 17; j++){ acc0[j] = 0ull; acc1[j] = 0ull; }

    const float4* ap = (const float4*)em;            // row stride 256 float4

    float4 areg[8];
    float  wreg[9];

    // ---- prologue: tile 0 -> regs -> smem buf 0 ----
    #pragma unroll
    for (int q = 0; q < 8; q++){                     // f = q*64+tid: row=f>>2, c4=f&3 (coalesced)
        int f = q*64 + tid, r = f >> 2, c4 = f & 3;
        areg[q] = ap[(size_t)(row_base + r) * 256 + c4];
    }
    #pragma unroll
    for (int q = 0; q < 9; q++){
        int i = tid + 64*q, kk = i / 36, j = i - kk*36;
        wreg[q] = (j < NT) ? W[(size_t)kk * NT + j] : 0.f;
    }
    #pragma unroll
    for (int q = 0; q < 8; q++){
        int f = q*64 + tid, r = f >> 2, c4 = f & 3;
        *(float4*)&Ast[0][r*AST + c4*4] = areg[q];
    }
    {
        float* Wf = (float*)&Wt[0][0][0];
        #pragma unroll
        for (int q = 0; q < 9; q++){
            int i = tid + 64*q, kk = i / 36, j = i - kk*36;
            Wf[kk*36 + j] = wreg[q];
        }
    }
    __syncthreads();

    #pragma unroll 1
    for (int kt = 0; kt < Dn/KTG; kt++){
        const int cur = kt & 1, nxt = cur ^ 1;
        const bool more = (kt < Dn/KTG - 1);

        if (more){
            #pragma unroll
            for (int q = 0; q < 8; q++){
                int f = q*64 + tid, r = f >> 2, c4 = f & 3;
                areg[q] = ap[(size_t)(row_base + r) * 256 + (kt+1)*4 + c4];
            }
            const float* wsrc = W + (size_t)(kt+1) * KTG * NT;
            #pragma unroll
            for (int q = 0; q < 9; q++){
                int i = tid + 64*q, kk = i / 36, j = i - kk*36;
                wreg[q] = (j < NT) ? wsrc[(size_t)kk * NT + j] : 0.f;
            }
        }

        // ---- compute tile kt from smem (conflict-free LDS.128) ----
        #pragma unroll
        for (int k4 = 0; k4 < 4; k4++){
            float4 a0 = *(const float4*)&Ast[cur][tid*AST + k4*4];
            float4 a1 = *(const float4*)&Ast[cur][(tid + 64)*AST + k4*4];
            GU2P(a0.x, a1.x, k4*4+0);
            GU2P(a0.y, a1.y, k4*4+1);
            GU2P(a0.z, a1.z, k4*4+2);
            GU2P(a0.w, a1.w, k4*4+3);
        }

        if (more){
            #pragma unroll
            for (int q = 0; q < 8; q++){
                int f = q*64 + tid, r = f >> 2, c4 = f & 3;
                *(float4*)&Ast[nxt][r*AST + c4*4] = areg[q];
            }
            float* Wf = (float*)&Wt[nxt][0][0];
            #pragma unroll
            for (int q = 0; q < 9; q++){
                int i = tid + 64*q, kk = i / 36, j = i - kk*36;
                Wf[kk*36 + j] = wreg[q];
            }
            __syncthreads();   // double-buffered: one barrier per tile
        }
    }

    // ---- epilogue: 2 chunks of 64 rows, staged through smem for coalesced stores ----
    #pragma unroll
    for (int r = 0; r < 2; r++){
        const u64* acc = (r == 0) ? acc0 : acc1;
        #pragma unroll
        for (int j2 = 0; j2 < 17; j2++){
            float lo, hi;
            unpack2(acc[j2], lo, hi);
            int jl = 2*j2, jh = 2*j2 + 1;
            s_out[tid * NA + jl] = lo + s_bias[jl];
            if (jh < NA) s_out[tid * NA + jh] = hi + s_bias[jh];
        }
        __syncthreads();
        float* obase = out + 1 + ((size_t)blockIdx.x * 128 + 64*r) * NA;
        #pragma unroll
        for (int q = 0; q < NA; q++)
            obase[tid + 64*q] = s_out[tid + 64*q];
        __syncthreads();
    }
}

// ============================ CRF scan (fwd/bwd) + gold score ============================
// Reads logits from out[b][t][j] (coalesced across lanes), exp applied inline.
#define SCAN_BODY(PL, PH, EMJ, EM32, MK, DOT_W)                                \
{                                                                              \
    float p0v = __shfl_sync(0xffffffffu, PL, 0);                               \
    unsigned eb = __float_as_uint(p0v) >> 23;                                  \
    cnt += (int)eb - 127;                                                      \
    float scl = __uint_as_float((254u - eb) << 23);                            \
    float al0=0.f, al1=0.f, al2=0.f, al3=0.f;                                  \
    float ahh0=0.f, ahh1=0.f, ahh2=0.f, ahh3=0.f;                              \
    float wl = (DOT_W) ? (PL) * (EMJ)  : (PL);                                 \
    float wh = (DOT_W) ? (PH) * (EM32) : (PH);                                 \
    _Pragma("unroll")                                                          \
    for (int i = 0; i < 32; i += 4){                                           \
        float v0 = __shfl_sync(0xffffffffu, wl, i);                            \
        float v1 = __shfl_sync(0xffffffffu, wl, i+1);                          \
        float v2 = __shfl_sync(0xffffffffu, wl, i+2);                          \
        float v3 = __shfl_sync(0xffffffffu, wl, i+3);                          \
        al0 += v0*E_l[i];   ahh0 += v0*E_h[i];                                 \
        al1 += v1*E_l[i+1]; ahh1 += v1*E_h[i+1];                               \
        al2 += v2*E_l[i+2]; ahh2 += v2*E_h[i+2];                               \
        al3 += v3*E_l[i+3]; ahh3 += v3*E_h[i+3];                               \
    }                                                                          \
    al0 += wh*E_l[32]; ahh0 += wh*E_h[32];                                     \
    float sl = (al0+al1)+(al2+al3);                                            \
    float sh = (ahh0+ahh1)+(ahh2+ahh3);                                        \
    float nl, nh;                                                              \
    if (DOT_W){ nl = sl*scl; nh = sh*scl; }                                    \
    else      { nl = sl*((EMJ)*scl); nh = sh*((EM32)*scl); }                   \
    if ((MK) == 0.f){ nl = (PL)*scl; nh = (PH)*scl; }                          \
    PL = nl; PH = nh;                                                          \
}

__global__ __launch_bounds__(32)
void scan_kernel(const float* __restrict__ T, const float* __restrict__ mask,
                 const int* __restrict__ tags, const float* __restrict__ outp)
{
    const int blk = blockIdx.x;
    const int j   = threadIdx.x;

    if (blk >= 2 * Bn){
        // ---- gold-path score for batch (blk - 2*Bn) ----
        int b = blk - 2 * Bn, lane = j;
        float partial = 0.f;
        for (int t = lane; t < Sn; t += 32){
            int   tg = tags[b*Sn + t];
            float e  = outp[1 + ((size_t)b*Sn + t)*NA + tg];
            if (t == 0){
                partial += T[BOSI*NT + tg] + e;
            } else {
                int tgp = tags[b*Sn + t - 1];
                partial += (e + T[tgp*NT + tg]) * mask[b*Sn + t];
            }
        }
        #pragma unroll
        for (int o = 16; o; o >>= 1) partial += __shfl_xor_sync(0xffffffffu, partial, o);
        if (lane == 0) g_score[b] = partial;
        return;
    }

    const int b   = blk >> 1;
    const int dir = blk & 1;

    float E_l[NA], E_h[NA];
    if (dir == 0){
        #pragma unroll
        for (int i = 0; i < NA; i++){
            E_l[i] = __expf(T[i*NT + j]);
            E_h[i] = __expf(T[i*NT + 32]);
        }
    } else {
        #pragma unroll
        for (int s = 0; s < NA; s++){
            E_l[s] = __expf(T[j*NT + s]);
            E_h[s] = __expf(T[32*NT + s]);
        }
    }

    const float* eb_base = outp + 1 + (size_t)b * Sn * NA;   // [t][j], lane-coalesced
    const float4* mp4 = (const float4*)(mask + (size_t)b * Sn);

    int cnt = 0;

    if (dir == 0){
        float emc[4], e3c[4];
        #pragma unroll
        for (int d = 0; d < 4; d++){
            emc[d] = eb_base[d*NA + j];
            e3c[d] = eb_base[d*NA + 32];
        }
        float4 mkc = mp4[0];

        float pl = __expf(T[BOSI*NT + j])  * __expf(emc[0]);
        float ph = __expf(T[BOSI*NT + 32]) * __expf(e3c[0]);

        float emn[4], e3n[4]; float4 mkn;
        #pragma unroll
        for (int d = 0; d < 4; d++){
            emn[d] = eb_base[(4 + d)*NA + j];
            e3n[d] = eb_base[(4 + d)*NA + 32];
        }
        mkn = mp4[1];

        SCAN_BODY(pl, ph, __expf(emc[1]), __expf(e3c[1]), mkc.y, 0);
        SCAN_BODY(pl, ph, __expf(emc[2]), __expf(e3c[2]), mkc.z, 0);
        SCAN_BODY(pl, ph, __expf(emc[3]), __expf(e3c[3]), mkc.w, 0);

        for (int g = 1; g < 128; g++){
            #pragma unroll
            for (int d = 0; d < 4; d++){ emc[d] = emn[d]; e3c[d] = e3n[d]; }
            mkc = mkn;
            if (g + 1 < 128){
                #pragma unroll
                for (int d = 0; d < 4; d++){
                    emn[d] = eb_base[((g+1)*4 + d)*NA + j];
                    e3n[d] = eb_base[((g+1)*4 + d)*NA + 32];
                }
                mkn = mp4[g+1];
            }
            SCAN_BODY(pl, ph, __expf(emc[0]), __expf(e3c[0]), mkc.x, 0);
            SCAN_BODY(pl, ph, __expf(emc[1]), __expf(e3c[1]), mkc.y, 0);
            SCAN_BODY(pl, ph, __expf(emc[2]), __expf(e3c[2]), mkc.z, 0);
            SCAN_BODY(pl, ph, __expf(emc[3]), __expf(e3c[3]), mkc.w, 0);
        }
        g_pm[b][j] = pl;
        if (j == 0){ g_pm[b][32] = ph; g_cntf[b] = cnt; }
    } else {
        float vl = 1.f, vh = 1.f;

        float emc[4], e3c[4];
        #pragma unroll
        for (int d = 0; d < 4; d++){
            emc[d] = eb_base[(255*4 + d)*NA + j];
            e3c[d] = eb_base[(255*4 + d)*NA + 32];
        }
        float4 mkc = mp4[255];

        float emn[4], e3n[4]; float4 mkn;

        for (int g = 255; g >= 128; g--){
            if (g > 128){
                #pragma unroll
                for (int d = 0; d < 4; d++){
                    emn[d] = eb_base[((g-1)*4 + d)*NA + j];
                    e3n[d] = eb_base[((g-1)*4 + d)*NA + 32];
                }
                mkn = mp4[g-1];
            }
            SCAN_BODY(vl, vh, __expf(emc[3]), __expf(e3c[3]), mkc.w, 1);
            SCAN_BODY(vl, vh, __expf(emc[2]), __expf(e3c[2]), mkc.z, 1);
            SCAN_BODY(vl, vh, __expf(emc[1]), __expf(e3c[1]), mkc.y, 1);
            SCAN_BODY(vl, vh, __expf(emc[0]), __expf(e3c[0]), mkc.x, 1);
            #pragma unroll
            for (int d = 0; d < 4; d++){ emc[d] = emn[d]; e3c[d] = e3n[d]; }
            mkc = mkn;
        }
        g_vm[b][j] = vl;
        if (j == 0){ g_vm[b][32] = vh; g_cntb[b] = cnt; }
    }
}

// ============================ combine + loss ============================
__global__ __launch_bounds__(32)
void loss_kernel(float* __restrict__ out)
{
    int lane = threadIdx.x;
    double v = 0.0;
    #pragma unroll
    for (int h = 0; h < 2; h++){
        int b = lane + 32*h;
        double dot = 0.0;
        #pragma unroll
        for (int i = 0; i < NA; i++) dot += (double)g_pm[b][i] * (double)g_vm[b][i];
        double part = (double)(g_cntf[b] + g_cntb[b]) * 0.6931471805599453 + log(dot);
        v += part - (double)g_score[b];
    }
    #pragma unroll
    for (int o = 16; o; o >>= 1) v += __shfl_xor_sync(0xffffffffu, v, o);
    if (lane == 0) out[0] = (float)v;
}

// ============================ launch ============================
extern "C" void kernel_launch(void* const* d_in, const int* in_sizes, int n_in,
                              void* d_out, int out_size)
{
    const float* em   = (const float*)d_in[0];   // (B,S,D)
    const int*   tags = (const int*)  d_in[1];   // (B,S)
    const float* mask = (const float*)d_in[2];   // (B,S)
    const float* W    = (const float*)d_in[3];   // (D,N)
    const float* bias = (const float*)d_in[4];   // (N,)
    const float* T    = (const float*)d_in[5];   // (N,N)
    float* out = (float*)d_out;                  // [loss, logits(B,S,33)]

    gemm_kernel <<<(Bn*Sn)/128, 64>>>(em, W, bias, out);
    scan_kernel <<<3*Bn, 32>>>(T, mask, tags, out);
    loss_kernel <<<1, 32>>>(out);
}